// round 3
// baseline (speedup 1.0000x reference)
#include <cuda_runtime.h>
#include <cstdint>
#include <cstdio>

#define Bsz   4
#define Sln   8192
#define DIM   512
#define NH    8
#define NKV   4
#define HD    64
#define NTOK  (Bsz*Sln)          // 32768
#define KVDIM (NKV*HD)           // 256

// ---------------- scratch (device globals; no allocation allowed) ----------
__device__ float g_xn[(size_t)NTOK * DIM];   // x after rmsnorm; later reused as Y
__device__ float g_q [(size_t)NTOK * DIM];   // q -> Q_lin (in place)
__device__ float g_k [(size_t)NTOK * KVDIM]; // k -> K_lin (in place)
__device__ float g_v [(size_t)NTOK * KVDIM]; // v (raw)
__device__ float g_cos[Sln * 32];
__device__ float g_sin[Sln * 32];
__device__ float g_pkv[64 * 16 * 64];        // partial KV sums [chunk][b*4+hk][d]
__device__ float g_pks[64 * 16 * 64];        // partial K sums
__device__ float g_kv [16 * 64];             // KV[b*4+hk][d]
__device__ float g_ks [16 * 64];             // K_sum[b*4+hk][d]

// ---------------- RMSNorm: one block per token --------------------------------
__global__ __launch_bounds__(128) void rmsnorm_kernel(const float* __restrict__ x,
                                                      const float* __restrict__ w) {
    int t = blockIdx.x;
    const float4* xr = (const float4*)(x + (size_t)t * DIM);
    float4 v = xr[threadIdx.x];
    float ss = v.x*v.x + v.y*v.y + v.z*v.z + v.w*v.w;
    #pragma unroll
    for (int o = 16; o; o >>= 1) ss += __shfl_xor_sync(0xffffffffu, ss, o);
    __shared__ float sred[4];
    if ((threadIdx.x & 31) == 0) sred[threadIdx.x >> 5] = ss;
    __syncthreads();
    float tot = sred[0] + sred[1] + sred[2] + sred[3];
    float rs = rsqrtf(tot * (1.0f / DIM) + 1e-6f);
    const float4* wr = (const float4*)w;
    float4 wv = wr[threadIdx.x];
    float4 o;
    o.x = v.x * rs * wv.x;
    o.y = v.y * rs * wv.y;
    o.z = v.z * rs * wv.z;
    o.w = v.w * rs * wv.w;
    ((float4*)(g_xn + (size_t)t * DIM))[threadIdx.x] = o;
}

// ---------------- RoPE tables --------------------------------------------------
__global__ void rope_table_kernel() {
    int idx = blockIdx.x * blockDim.x + threadIdx.x;
    if (idx >= Sln * 32) return;
    int si = idx >> 5, j = idx & 31;
    float inv = powf(10000.0f, -(float)j * (1.0f / 32.0f));
    float ang = (float)si * inv;
    g_cos[idx] = cosf(ang);
    g_sin[idx] = sinf(ang);
}

// ---------------- SGEMM: C[M,N] = A[M,K] * B[N,K]^T  (both K-innermost) --------
// 128x128 tile, BK=16, 256 threads, 8x8 per thread. M,N multiples of 128, K of 16.
__global__ __launch_bounds__(256) void sgemm_tn(const float* __restrict__ A,
                                                const float* __restrict__ B,
                                                float* __restrict__ C,
                                                int M, int N, int K) {
    __shared__ float As[16][132];
    __shared__ float Bs[16][132];
    const int tid = threadIdx.x;
    const int bm = blockIdx.y * 128;
    const int bn = blockIdx.x * 128;
    const int tx = tid & 15;       // 0..15
    const int ty = tid >> 4;       // 0..15
    float acc[8][8] = {};
    for (int k0 = 0; k0 < K; k0 += 16) {
        #pragma unroll
        for (int i = 0; i < 2; i++) {
            int l = tid + i * 256;          // 0..511
            int row = l >> 2;               // 0..127
            int c = (l & 3) << 2;           // 0,4,8,12
            float4 va = *(const float4*)(A + (size_t)(bm + row) * K + k0 + c);
            As[c + 0][row] = va.x; As[c + 1][row] = va.y;
            As[c + 2][row] = va.z; As[c + 3][row] = va.w;
            float4 vb = *(const float4*)(B + (size_t)(bn + row) * K + k0 + c);
            Bs[c + 0][row] = vb.x; Bs[c + 1][row] = vb.y;
            Bs[c + 2][row] = vb.z; Bs[c + 3][row] = vb.w;
        }
        __syncthreads();
        #pragma unroll
        for (int kk = 0; kk < 16; kk++) {
            float a[8], b[8];
            *(float4*)(a)     = *(const float4*)&As[kk][ty * 8];
            *(float4*)(a + 4) = *(const float4*)&As[kk][ty * 8 + 4];
            *(float4*)(b)     = *(const float4*)&Bs[kk][tx * 8];
            *(float4*)(b + 4) = *(const float4*)&Bs[kk][tx * 8 + 4];
            #pragma unroll
            for (int i = 0; i < 8; i++)
                #pragma unroll
                for (int j = 0; j < 8; j++)
                    acc[i][j] += a[i] * b[j];
        }
        __syncthreads();
    }
    #pragma unroll
    for (int i = 0; i < 8; i++) {
        float4 o0 = {acc[i][0], acc[i][1], acc[i][2], acc[i][3]};
        float4 o1 = {acc[i][4], acc[i][5], acc[i][6], acc[i][7]};
        float* crow = C + (size_t)(bm + ty * 8 + i) * N + bn + tx * 8;
        *(float4*)(crow)     = o0;
        *(float4*)(crow + 4) = o1;
    }
}

// ---------------- RoPE + phi (elu+1), in place on q and k ----------------------
// idx -> (t, slot, j): slot 0..7 = q heads, 8..11 = k heads; j = rotary pair
__global__ __launch_bounds__(256) void rope_phi_kernel() {
    int idx = blockIdx.x * blockDim.x + threadIdx.x;   // NTOK*12*32 total
    int j = idx & 31;
    int rest = idx >> 5;
    int slot = rest % 12;
    int t = rest / 12;
    int s = t & (Sln - 1);
    float c  = g_cos[(s << 5) + j];
    float sn = g_sin[(s << 5) + j];
    float2* base;
    if (slot < 8) base = (float2*)(g_q + (size_t)t * DIM + slot * HD) + j;
    else          base = (float2*)(g_k + (size_t)t * KVDIM + (slot - 8) * HD) + j;
    float2 v = *base;
    float orr = v.x * c - v.y * sn;
    float oi  = v.x * sn + v.y * c;
    v.x = orr > 0.f ? orr + 1.f : expf(orr);
    v.y = oi  > 0.f ? oi  + 1.f : expf(oi);
    *base = v;
}

// ---------------- KV / K_sum reduction, pass 1 (deterministic, no atomics) -----
// block = (chunk 0..63, bhk 0..15); 256 threads: d = tid&63, slice = tid>>6
__global__ __launch_bounds__(256) void kv_reduce1_kernel() {
    int chunk = blockIdx.x >> 4;
    int bhk   = blockIdx.x & 15;
    int b = bhk >> 2, hk = bhk & 3;
    int d  = threadIdx.x & 63;
    int sl = threadIdx.x >> 6;
    float akv = 0.f, ak = 0.f;
    int s0 = chunk * 128 + sl * 32;
    #pragma unroll 4
    for (int i = 0; i < 32; i++) {
        size_t off = ((size_t)(b * Sln + s0 + i)) * KVDIM + hk * HD + d;
        float kk = g_k[off];
        akv += kk * g_v[off];
        ak  += kk;
    }
    __shared__ float skv[256], sks[256];
    skv[threadIdx.x] = akv; sks[threadIdx.x] = ak;
    __syncthreads();
    if (sl == 0) {
        akv = skv[d] + skv[64 + d] + skv[128 + d] + skv[192 + d];
        ak  = sks[d] + sks[64 + d] + sks[128 + d] + sks[192 + d];
        g_pkv[(size_t)blockIdx.x * 64 + d] = akv;
        g_pks[(size_t)blockIdx.x * 64 + d] = ak;
    }
}

// ---------------- pass 2: sum 64 chunks ----------------------------------------
__global__ void kv_reduce2_kernel() {
    int bhk = blockIdx.x;        // 0..15
    int d = threadIdx.x;         // 0..63
    float akv = 0.f, ak = 0.f;
    #pragma unroll 8
    for (int c = 0; c < 64; c++) {
        akv += g_pkv[((c << 4) + bhk) * 64 + d];
        ak  += g_pks[((c << 4) + bhk) * 64 + d];
    }
    g_kv[bhk * 64 + d] = akv;
    g_ks[bhk * 64 + d] = ak;
}

// ---------------- per-token: Z = <Qlin, Ksum>; Y = Qlin*KV/(Z+eps) -------------
// block per token; warp per head (8 warps); lane covers d and d+32
__global__ __launch_bounds__(256) void attn_out_kernel() {
    int t = blockIdx.x;
    int h = threadIdx.x >> 5;
    int lane = threadIdx.x & 31;
    int b = t >> 13;
    int hk = h >> 1;
    size_t qoff = (size_t)t * DIM + h * HD;
    float q0 = g_q[qoff + lane];
    float q1 = g_q[qoff + 32 + lane];
    int koff = (b * 4 + hk) * 64;
    float z = q0 * g_ks[koff + lane] + q1 * g_ks[koff + 32 + lane];
    #pragma unroll
    for (int o = 16; o; o >>= 1) z += __shfl_xor_sync(0xffffffffu, z, o);
    float inv = 1.0f / (z + 1e-6f);
    g_xn[qoff + lane]      = q0 * g_kv[koff + lane]      * inv;   // Y reuses g_xn
    g_xn[qoff + 32 + lane] = q1 * g_kv[koff + 32 + lane] * inv;
}

// ---------------- host launcher -----------------------------------------------
extern "C" void kernel_launch(void* const* d_in, const int* in_sizes, int n_in,
                              void* d_out, int out_size) {
    (void)in_sizes; (void)n_in; (void)out_size;
    const float* x  = (const float*)d_in[0];
    const float* nw = (const float*)d_in[1];
    const float* wq = (const float*)d_in[2];
    const float* wk = (const float*)d_in[3];
    const float* wv = (const float*)d_in[4];
    const float* wo = (const float*)d_in[5];
    float* out = (float*)d_out;

    float *p_xn, *p_q, *p_k, *p_v;
    cudaGetSymbolAddress((void**)&p_xn, g_xn);
    cudaGetSymbolAddress((void**)&p_q,  g_q);
    cudaGetSymbolAddress((void**)&p_k,  g_k);
    cudaGetSymbolAddress((void**)&p_v,  g_v);

    // 1. RoPE tables (cheap, recomputed every call for determinism)
    rope_table_kernel<<<(Sln * 32 + 255) / 256, 256>>>();
    // 2. RMSNorm
    rmsnorm_kernel<<<NTOK, 128>>>(x, nw);
    // 3. QKV GEMMs
    sgemm_tn<<<dim3(DIM / 128,   NTOK / 128), 256>>>(p_xn, wq, p_q, NTOK, DIM,   DIM);
    sgemm_tn<<<dim3(KVDIM / 128, NTOK / 128), 256>>>(p_xn, wk, p_k, NTOK, KVDIM, DIM);
    sgemm_tn<<<dim3(KVDIM / 128, NTOK / 128), 256>>>(p_xn, wv, p_v, NTOK, KVDIM, DIM);
    // 4. RoPE + phi on q,k (in place)
    rope_phi_kernel<<<(NTOK * 12 * 32) / 256, 256>>>();
    // 5. Global reductions KV, K_sum
    kv_reduce1_kernel<<<64 * 16, 256>>>();
    kv_reduce2_kernel<<<16, 64>>>();
    // 6. Per-token normalize -> Y (into g_xn)
    attn_out_kernel<<<NTOK, 256>>>();
    // 7. Output GEMM
    sgemm_tn<<<dim3(DIM / 128, NTOK / 128), 256>>>(p_xn, wo, out, NTOK, DIM, DIM);
}

// round 6
// speedup vs baseline: 2.1091x; 2.1091x over previous
#include <cuda_runtime.h>
#include <cstdint>
#include <cstdio>

#define Bsz   4
#define Sln   8192
#define DIM   512
#define NH    8
#define NKV   4
#define HD    64
#define NTOK  (Bsz*Sln)          // 32768
#define KVDIM (NKV*HD)           // 256
#define GK    512
#define BK    32

// ---------------- scratch (device globals; no allocation allowed) ----------
__device__ float g_xn[(size_t)NTOK * DIM];   // x after rmsnorm; later reused as Y
__device__ float g_q [(size_t)NTOK * DIM];   // q -> Q_lin (in place)
__device__ float g_k [(size_t)NTOK * KVDIM]; // k -> K_lin (in place)
__device__ float g_v [(size_t)NTOK * KVDIM]; // v (raw)
__device__ float g_cos[Sln * 32];
__device__ float g_sin[Sln * 32];
__device__ float g_pkv[64 * 16 * 64];
__device__ float g_pks[64 * 16 * 64];
__device__ float g_kv [16 * 64];
__device__ float g_ks [16 * 64];

// ======================= tf32 mma.sync GEMM =======================
__device__ __forceinline__ float f2tf(float f) {
    uint32_t o;
    asm("cvt.rn.tf32.f32 %0, %1;" : "=r"(o) : "f"(f));
    return __uint_as_float(o);
}
__device__ __forceinline__ void mma_tf32(float* d, const uint32_t* a, const uint32_t* b) {
    asm volatile(
        "mma.sync.aligned.m16n8k8.row.col.f32.tf32.tf32.f32 "
        "{%0,%1,%2,%3}, {%4,%5,%6,%7}, {%8,%9}, {%0,%1,%2,%3};"
        : "+f"(d[0]), "+f"(d[1]), "+f"(d[2]), "+f"(d[3])
        : "r"(a[0]), "r"(a[1]), "r"(a[2]), "r"(a[3]), "r"(b[0]), "r"(b[1]));
}

// C[M,N] = A[M,512] * B[N,512]^T. Block 128x128, BK=32, 256 thr, 8 warps (4m x 2n).
// SMEM per stage: A-frag 4096 fl (16KB) + B-frag 4096 fl (16KB); double buffered = 64KB.
// A frag unit (16B) addr: ((mt*4+ks)*32 + (lane^ks)); lane's 4 regs contiguous.
// B frag unit (8B)  addr: ((nt*4+ks)*32 + (lane^ks)); lane's 2 regs contiguous.
#define G_SMEM_BYTES 65536

__global__ __launch_bounds__(256) void gemm_tf32mma(const float* __restrict__ A,
                                                    const float* __restrict__ B,
                                                    float* __restrict__ C, int N) {
    extern __shared__ float sm[];
    const int tid  = threadIdx.x;
    const int wid  = tid >> 5, lane = tid & 31;
    const int wm   = wid & 3,  wn   = wid >> 2;
    const int bm   = blockIdx.y * 128;
    const int bn   = blockIdx.x * 128;
    const float* Ag = A + (size_t)bm * GK;
    const float* Bg = B + (size_t)bn * GK;

    float acc[2][8][4];
    #pragma unroll
    for (int m = 0; m < 2; m++)
        #pragma unroll
        for (int j = 0; j < 8; j++)
            #pragma unroll
            for (int r = 0; r < 4; r++) acc[m][j][r] = 0.f;

    float4 va[4], vb[4];

#define LOADG(s)                                                                  \
    {                                                                             \
        const float* Ap = Ag + (s) * BK;                                          \
        const float* Bp = Bg + (s) * BK;                                          \
        _Pragma("unroll")                                                         \
        for (int i = 0; i < 4; i++) {                                             \
            int idx = tid + i * 256, row = idx >> 3, c4 = idx & 7;                \
            va[i] = *(const float4*)(Ap + (size_t)row * GK + c4 * 4);             \
            vb[i] = *(const float4*)(Bp + (size_t)row * GK + c4 * 4);             \
        }                                                                         \
    }

#define STORES(buf)                                                               \
    {                                                                             \
        float* sA = sm + (buf) * 8192;                                            \
        float* sB = sA + 4096;                                                    \
        _Pragma("unroll")                                                         \
        for (int i = 0; i < 4; i++) {                                             \
            int idx = tid + i * 256, row = idx >> 3, c4 = idx & 7;                \
            int ks = c4 >> 1, khi = c4 & 1;                                       \
            int mt = row >> 4, hi = (row >> 3) & 1, g = row & 7;                  \
            float* pa = sA + ((mt * 4 + ks) * 32) * 4 + hi + 2 * khi;             \
            pa[((g * 4 + 0) ^ ks) * 4] = f2tf(va[i].x);                           \
            pa[((g * 4 + 1) ^ ks) * 4] = f2tf(va[i].y);                           \
            pa[((g * 4 + 2) ^ ks) * 4] = f2tf(va[i].z);                           \
            pa[((g * 4 + 3) ^ ks) * 4] = f2tf(va[i].w);                           \
            int nt = row >> 3, gb = row & 7;                                      \
            float* pb = sB + ((nt * 4 + ks) * 32) * 2 + khi;                      \
            pb[((gb * 4 + 0) ^ ks) * 2] = f2tf(vb[i].x);                          \
            pb[((gb * 4 + 1) ^ ks) * 2] = f2tf(vb[i].y);                          \
            pb[((gb * 4 + 2) ^ ks) * 2] = f2tf(vb[i].z);                          \
            pb[((gb * 4 + 3) ^ ks) * 2] = f2tf(vb[i].w);                          \
        }                                                                         \
    }

#define COMPUTE(buf)                                                              \
    {                                                                             \
        const float* sA = sm + (buf) * 8192;                                      \
        const float* sB = sA + 4096;                                              \
        _Pragma("unroll")                                                         \
        for (int ks = 0; ks < 4; ks++) {                                          \
            uint32_t af[2][4], bf[8][2];                                          \
            _Pragma("unroll")                                                     \
            for (int m = 0; m < 2; m++) {                                         \
                float4 t = *(const float4*)(sA +                                  \
                    (((wm * 2 + m) * 4 + ks) * 32 + (lane ^ ks)) * 4);            \
                af[m][0] = __float_as_uint(t.x); af[m][1] = __float_as_uint(t.y); \
                af[m][2] = __float_as_uint(t.z); af[m][3] = __float_as_uint(t.w); \
            }                                                                     \
            _Pragma("unroll")                                                     \
            for (int j = 0; j < 8; j++) {                                         \
                float2 t = *(const float2*)(sB +                                  \
                    (((wn * 8 + j) * 4 + ks) * 32 + (lane ^ ks)) * 2);            \
                bf[j][0] = __float_as_uint(t.x); bf[j][1] = __float_as_uint(t.y); \
            }                                                                     \
            _Pragma("unroll")                                                     \
            for (int m = 0; m < 2; m++)                                           \
                _Pragma("unroll")                                                 \
                for (int j = 0; j < 8; j++)                                       \
                    mma_tf32(acc[m][j], af[m], bf[j]);                            \
        }                                                                         \
    }

    LOADG(0);
    STORES(0);
    __syncthreads();
    #pragma unroll 2
    for (int s = 0; s < 16; s++) {
        if (s < 15) LOADG(s + 1);
        COMPUTE(s & 1);
        if (s < 15) {
            STORES((s + 1) & 1);
            __syncthreads();
        }
    }

    // epilogue: c0,c1 -> (row g, cols 2tg,2tg+1); c2,c3 -> (row g+8)
    const int g = lane >> 2, tg = lane & 3;
    #pragma unroll
    for (int m = 0; m < 2; m++) {
        float* cr0 = C + (size_t)(bm + wm * 32 + m * 16 + g) * N + bn + wn * 64;
        float* cr1 = cr0 + (size_t)8 * N;
        #pragma unroll
        for (int j = 0; j < 8; j++) {
            float2 o0 = {acc[m][j][0], acc[m][j][1]};
            float2 o1 = {acc[m][j][2], acc[m][j][3]};
            *(float2*)(cr0 + j * 8 + tg * 2) = o0;
            *(float2*)(cr1 + j * 8 + tg * 2) = o1;
        }
    }
#undef LOADG
#undef STORES
#undef COMPUTE
}

// ---------------- RMSNorm: one block per token --------------------------------
__global__ __launch_bounds__(128) void rmsnorm_kernel(const float* __restrict__ x,
                                                      const float* __restrict__ w) {
    int t = blockIdx.x;
    const float4* xr = (const float4*)(x + (size_t)t * DIM);
    float4 v = xr[threadIdx.x];
    float ss = v.x*v.x + v.y*v.y + v.z*v.z + v.w*v.w;
    #pragma unroll
    for (int o = 16; o; o >>= 1) ss += __shfl_xor_sync(0xffffffffu, ss, o);
    __shared__ float sred[4];
    if ((threadIdx.x & 31) == 0) sred[threadIdx.x >> 5] = ss;
    __syncthreads();
    float tot = sred[0] + sred[1] + sred[2] + sred[3];
    float rs = rsqrtf(tot * (1.0f / DIM) + 1e-6f);
    const float4* wr = (const float4*)w;
    float4 wv = wr[threadIdx.x];
    float4 o;
    o.x = v.x * rs * wv.x;
    o.y = v.y * rs * wv.y;
    o.z = v.z * rs * wv.z;
    o.w = v.w * rs * wv.w;
    ((float4*)(g_xn + (size_t)t * DIM))[threadIdx.x] = o;
}

// ---------------- RoPE tables --------------------------------------------------
__global__ void rope_table_kernel() {
    int idx = blockIdx.x * blockDim.x + threadIdx.x;
    if (idx >= Sln * 32) return;
    int si = idx >> 5, j = idx & 31;
    float inv = powf(10000.0f, -(float)j * (1.0f / 32.0f));
    float ang = (float)si * inv;
    g_cos[idx] = cosf(ang);
    g_sin[idx] = sinf(ang);
}

// ---------------- RoPE + phi (elu+1), in place on q and k ----------------------
__global__ __launch_bounds__(256) void rope_phi_kernel() {
    int idx = blockIdx.x * blockDim.x + threadIdx.x;   // NTOK*12*32 total
    int j = idx & 31;
    int rest = idx >> 5;
    int slot = rest % 12;
    int t = rest / 12;
    int s = t & (Sln - 1);
    float c  = g_cos[(s << 5) + j];
    float sn = g_sin[(s << 5) + j];
    float2* base;
    if (slot < 8) base = (float2*)(g_q + (size_t)t * DIM + slot * HD) + j;
    else          base = (float2*)(g_k + (size_t)t * KVDIM + (slot - 8) * HD) + j;
    float2 v = *base;
    float orr = v.x * c - v.y * sn;
    float oi  = v.x * sn + v.y * c;
    v.x = orr > 0.f ? orr + 1.f : expf(orr);
    v.y = oi  > 0.f ? oi  + 1.f : expf(oi);
    *base = v;
}

// ---------------- KV / K_sum reduction, pass 1 ---------------------------------
__global__ __launch_bounds__(256) void kv_reduce1_kernel() {
    int chunk = blockIdx.x >> 4;
    int bhk   = blockIdx.x & 15;
    int b = bhk >> 2, hk = bhk & 3;
    int d  = threadIdx.x & 63;
    int sl = threadIdx.x >> 6;
    float akv = 0.f, ak = 0.f;
    int s0 = chunk * 128 + sl * 32;
    #pragma unroll 4
    for (int i = 0; i < 32; i++) {
        size_t off = ((size_t)(b * Sln + s0 + i)) * KVDIM + hk * HD + d;
        float kk = g_k[off];
        akv += kk * g_v[off];
        ak  += kk;
    }
    __shared__ float skv[256], sks[256];
    skv[threadIdx.x] = akv; sks[threadIdx.x] = ak;
    __syncthreads();
    if (sl == 0) {
        akv = skv[d] + skv[64 + d] + skv[128 + d] + skv[192 + d];
        ak  = sks[d] + sks[64 + d] + sks[128 + d] + sks[192 + d];
        g_pkv[(size_t)blockIdx.x * 64 + d] = akv;
        g_pks[(size_t)blockIdx.x * 64 + d] = ak;
    }
}

// ---------------- pass 2 -------------------------------------------------------
__global__ void kv_reduce2_kernel() {
    int bhk = blockIdx.x;
    int d = threadIdx.x;
    float akv = 0.f, ak = 0.f;
    #pragma unroll 8
    for (int c = 0; c < 64; c++) {
        akv += g_pkv[((c << 4) + bhk) * 64 + d];
        ak  += g_pks[((c << 4) + bhk) * 64 + d];
    }
    g_kv[bhk * 64 + d] = akv;
    g_ks[bhk * 64 + d] = ak;
}

// ---------------- per-token normalize -> Y -------------------------------------
__global__ __launch_bounds__(256) void attn_out_kernel() {
    int t = blockIdx.x;
    int h = threadIdx.x >> 5;
    int lane = threadIdx.x & 31;
    int b = t >> 13;
    int hk = h >> 1;
    size_t qoff = (size_t)t * DIM + h * HD;
    float q0 = g_q[qoff + lane];
    float q1 = g_q[qoff + 32 + lane];
    int koff = (b * 4 + hk) * 64;
    float z = q0 * g_ks[koff + lane] + q1 * g_ks[koff + 32 + lane];
    #pragma unroll
    for (int o = 16; o; o >>= 1) z += __shfl_xor_sync(0xffffffffu, z, o);
    float inv = 1.0f / (z + 1e-6f);
    g_xn[qoff + lane]      = q0 * g_kv[koff + lane]      * inv;
    g_xn[qoff + 32 + lane] = q1 * g_kv[koff + 32 + lane] * inv;
}

// ---------------- host launcher -----------------------------------------------
extern "C" void kernel_launch(void* const* d_in, const int* in_sizes, int n_in,
                              void* d_out, int out_size) {
    (void)in_sizes; (void)n_in; (void)out_size;
    const float* x  = (const float*)d_in[0];
    const float* nw = (const float*)d_in[1];
    const float* wq = (const float*)d_in[2];
    const float* wk = (const float*)d_in[3];
    const float* wv = (const float*)d_in[4];
    const float* wo = (const float*)d_in[5];
    float* out = (float*)d_out;

    float *p_xn, *p_q, *p_k, *p_v;
    cudaGetSymbolAddress((void**)&p_xn, g_xn);
    cudaGetSymbolAddress((void**)&p_q,  g_q);
    cudaGetSymbolAddress((void**)&p_k,  g_k);
    cudaGetSymbolAddress((void**)&p_v,  g_v);

    static int smem_set = 0;
    if (!smem_set) {
        cudaFuncSetAttribute(gemm_tf32mma, cudaFuncAttributeMaxDynamicSharedMemorySize,
                             G_SMEM_BYTES);
        smem_set = 1;
    }

    rope_table_kernel<<<(Sln * 32 + 255) / 256, 256>>>();
    rmsnorm_kernel<<<NTOK, 128>>>(x, nw);
    gemm_tf32mma<<<dim3(DIM / 128,   NTOK / 128), 256, G_SMEM_BYTES>>>(p_xn, wq, p_q, DIM);
    gemm_tf32mma<<<dim3(KVDIM / 128, NTOK / 128), 256, G_SMEM_BYTES>>>(p_xn, wk, p_k, KVDIM);
    gemm_tf32mma<<<dim3(KVDIM / 128, NTOK / 128), 256, G_SMEM_BYTES>>>(p_xn, wv, p_v, KVDIM);
    rope_phi_kernel<<<(NTOK * 12 * 32) / 256, 256>>>();
    kv_reduce1_kernel<<<64 * 16, 256>>>();
    kv_reduce2_kernel<<<16, 64>>>();
    attn_out_kernel<<<NTOK, 256>>>();
    gemm_tf32mma<<<dim3(DIM / 128, NTOK / 128), 256, G_SMEM_BYTES>>>(p_xn, wo, out, DIM);
}